// round 1
// baseline (speedup 1.0000x reference)
#include <cuda_runtime.h>
#include <math.h>

// Problem constants (fixed by the dataset)
#define NN 8192
#define DD 512

// SGEMM tile config: 128x128 block tile, BK=8, 8x8 per-thread microtile, 256 threads
#define BM 128
#define BN 128
#define BK 8
#define TM 8
#define TN 8

// C = s * X @ X^T, exploiting symmetry: only tiles with tileC >= tileR are
// computed; the mirrored tile is written from registers (transposed).
__global__ void __launch_bounds__(256, 2)
xxt_sym_kernel(const float* __restrict__ X,
               const float* __restrict__ rho_k,
               float* __restrict__ C)
{
    const int tileC = blockIdx.x;
    const int tileR = blockIdx.y;
    if (tileC < tileR) return;   // lower-triangle blocks exit immediately

    __shared__ float As[BK][BM];
    __shared__ float Bs[BK][BN];

    const int tid = threadIdx.x;
    const int tr  = tid >> 4;     // 0..15  (row group)
    const int tc  = tid & 15;     // 0..15  (col group)

    const int rowBase = tileR * BM;
    const int colBase = tileC * BN;

    // Cooperative tile load mapping: each thread loads one float4 per tile
    const int lr  = tid >> 1;        // 0..127
    const int lc4 = (tid & 1) * 4;   // 0 or 4

    const float* Aptr = X + (size_t)(rowBase + lr) * DD + lc4;
    const float* Bptr = X + (size_t)(colBase + lr) * DD + lc4;

    float acc[TM][TN];
#pragma unroll
    for (int i = 0; i < TM; i++)
#pragma unroll
        for (int j = 0; j < TN; j++) acc[i][j] = 0.0f;

    for (int k0 = 0; k0 < DD; k0 += BK) {
        const float4 a = *(const float4*)(Aptr + k0);
        const float4 b = *(const float4*)(Bptr + k0);
        As[lc4 + 0][lr] = a.x; As[lc4 + 1][lr] = a.y;
        As[lc4 + 2][lr] = a.z; As[lc4 + 3][lr] = a.w;
        Bs[lc4 + 0][lr] = b.x; Bs[lc4 + 1][lr] = b.y;
        Bs[lc4 + 2][lr] = b.z; Bs[lc4 + 3][lr] = b.w;
        __syncthreads();

#pragma unroll
        for (int k = 0; k < BK; k++) {
            float ra[TM], rb[TN];
#pragma unroll
            for (int i = 0; i < TM; i++) ra[i] = As[k][tr * TM + i];
#pragma unroll
            for (int j = 0; j < TN; j++) rb[j] = Bs[k][tc * TN + j];
#pragma unroll
            for (int i = 0; i < TM; i++)
#pragma unroll
                for (int j = 0; j < TN; j++)
                    acc[i][j] = fmaf(ra[i], rb[j], acc[i][j]);
        }
        __syncthreads();
    }

    const float s = __ldg(rho_k);   // rho_kernel[0], scalar broadcast

    const int r0 = rowBase + tr * TM;
    const int c0 = colBase + tc * TN;

    // Upper (or diagonal) tile: coalesced float4 stores
#pragma unroll
    for (int i = 0; i < TM; i++) {
#pragma unroll
        for (int j = 0; j < TN; j += 4) {
            float4 v;
            v.x = acc[i][j + 0] * s;
            v.y = acc[i][j + 1] * s;
            v.z = acc[i][j + 2] * s;
            v.w = acc[i][j + 3] * s;
            *(float4*)(C + (size_t)(r0 + i) * NN + c0 + j) = v;
        }
    }

    // Mirror tile (transposed) — each thread writes its 8x8 transposed block
    if (tileC != tileR) {
#pragma unroll
        for (int j = 0; j < TN; j++) {
#pragma unroll
            for (int i = 0; i < TM; i += 4) {
                float4 v;
                v.x = acc[i + 0][j] * s;
                v.y = acc[i + 1][j] * s;
                v.z = acc[i + 2][j] * s;
                v.w = acc[i + 3][j] * s;
                *(float4*)(C + (size_t)(c0 + j) * NN + r0 + i) = v;
            }
        }
    }
}

// Heads: one warp per row. Computes output_mu[row] and the softplus variance,
// writing the variance onto the covariance diagonal (after the GEMM).
__global__ void __launch_bounds__(256)
heads_kernel(const float* __restrict__ X,
             const float* __restrict__ muK,
             const float* __restrict__ varK,
             const float* __restrict__ muB,
             const float* __restrict__ varB,
             float* __restrict__ outMu,
             float* __restrict__ cov)
{
    const int gwarp = (blockIdx.x * blockDim.x + threadIdx.x) >> 5;
    const int lane  = threadIdx.x & 31;
    if (gwarp >= NN) return;

    const float* xr = X + (size_t)gwarp * DD;
    float sm = 0.0f, sv = 0.0f;

#pragma unroll
    for (int k = lane * 4; k < DD; k += 32 * 4) {
        const float4 xv = *(const float4*)(xr + k);
        const float4 m  = *(const float4*)(muK + k);
        const float4 v  = *(const float4*)(varK + k);
        sm = fmaf(xv.x, m.x, sm); sm = fmaf(xv.y, m.y, sm);
        sm = fmaf(xv.z, m.z, sm); sm = fmaf(xv.w, m.w, sm);
        sv = fmaf(xv.x, v.x, sv); sv = fmaf(xv.y, v.y, sv);
        sv = fmaf(xv.z, v.z, sv); sv = fmaf(xv.w, v.w, sv);
    }
#pragma unroll
    for (int o = 16; o; o >>= 1) {
        sm += __shfl_xor_sync(0xFFFFFFFFu, sm, o);
        sv += __shfl_xor_sync(0xFFFFFFFFu, sv, o);
    }
    if (lane == 0) {
        outMu[gwarp] = sm + __ldg(muB);
        const float z = sv + __ldg(varB);
        const float d = log1pf(expf(z)) + 1e-8f;
        cov[(size_t)gwarp * NN + gwarp] = d;
    }
}

extern "C" void kernel_launch(void* const* d_in, const int* in_sizes, int n_in,
                              void* d_out, int out_size)
{
    const float* x     = (const float*)d_in[0];  // [8192, 512]
    const float* mu_k  = (const float*)d_in[1];  // [512, 1]
    const float* rho_k = (const float*)d_in[2];  // [1]
    const float* var_k = (const float*)d_in[3];  // [512, 1]
    const float* mu_b  = (const float*)d_in[4];  // [1]
    const float* var_b = (const float*)d_in[5];  // [1]

    float* out_mu = (float*)d_out;        // [8192]
    float* cov    = out_mu + NN;          // [8192, 8192]

    dim3 grid(NN / BN, NN / BM);
    xxt_sym_kernel<<<grid, 256>>>(x, rho_k, cov);

    // heads after GEMM on same stream: diagonal overwrite is ordered correctly
    heads_kernel<<<NN / 8, 256>>>(x, mu_k, var_k, mu_b, var_b, out_mu, cov);
}

// round 3
// speedup vs baseline: 2.5051x; 2.5051x over previous
#include <cuda_runtime.h>
#include <cuda_bf16.h>
#include <math.h>
#include <stdint.h>

#define NN 8192
#define DD 512
#define NT 64            // 8192 / 128 tiles per dim
#define CHUNKS 16        // K chunks of 32
#define ROWB 2048        // bytes per packed row: 16 chunks * (32 H + 32 L) bf16

// Packed split-precision X: per row, per 32-k chunk: [32 bf16 H | 32 bf16 L] = 128B
__device__ __align__(128) __nv_bfloat16 g_P[(size_t)NN * 1024];

// ---------------- helpers ----------------
__device__ __forceinline__ uint32_t smem_u32(const void* p) {
    uint32_t a;
    asm("{ .reg .u64 t; cvta.to.shared.u64 t, %1; cvt.u32.u64 %0, t; }"
        : "=r"(a) : "l"(p));
    return a;
}
__device__ __forceinline__ void cp_async16(uint32_t sa, const void* ga) {
    asm volatile("cp.async.cg.shared.global [%0], [%1], 16;" :: "r"(sa), "l"(ga));
}
#define CP_COMMIT() asm volatile("cp.async.commit_group;" ::: "memory")
#define CP_WAIT(n)  asm volatile("cp.async.wait_group %0;" :: "n"(n) : "memory")

#define LDSM4(r0, r1, r2, r3, ad) \
    asm volatile("ldmatrix.sync.aligned.m8n8.x4.shared.b16 {%0,%1,%2,%3}, [%4];" \
                 : "=r"(r0), "=r"(r1), "=r"(r2), "=r"(r3) : "r"(ad))

#define MMA_BF16(d, a, b) \
    asm volatile("mma.sync.aligned.m16n8k16.row.col.f32.bf16.bf16.f32 " \
                 "{%0,%1,%2,%3}, {%4,%5,%6,%7}, {%8,%9}, {%0,%1,%2,%3};" \
                 : "+f"((d)[0]), "+f"((d)[1]), "+f"((d)[2]), "+f"((d)[3]) \
                 : "r"((a)[0]), "r"((a)[1]), "r"((a)[2]), "r"((a)[3]), \
                   "r"((b)[0]), "r"((b)[1]))

__device__ __forceinline__ uint32_t pack_bf2(float a, float b) {
    __nv_bfloat162 p;
    p.x = __float2bfloat16(a);
    p.y = __float2bfloat16(b);
    return *(uint32_t*)&p;
}

// ---------------- repack: X fp32 -> [H|L] packed bf16 chunks ----------------
__global__ void __launch_bounds__(256)
convert_kernel(const float* __restrict__ X) {
    const int gid = blockIdx.x * 256 + threadIdx.x;   // 8192*64 threads
    const int r = gid >> 6;
    const int t = gid & 63;
    const int c = t >> 2;        // chunk 0..15
    const int q = t & 3;         // 8-element slice in chunk
    const float* src = X + (size_t)r * DD + c * 32 + q * 8;
    float4 v0 = *(const float4*)(src);
    float4 v1 = *(const float4*)(src + 4);
    float f[8] = {v0.x, v0.y, v0.z, v0.w, v1.x, v1.y, v1.z, v1.w};

    uint32_t H[4], L[4];
#pragma unroll
    for (int i = 0; i < 4; i++) {
        float a = f[2 * i], b = f[2 * i + 1];
        __nv_bfloat16 ha = __float2bfloat16(a), hb = __float2bfloat16(b);
        float ra = a - __bfloat162float(ha);
        float rb = b - __bfloat162float(hb);
        __nv_bfloat162 hp; hp.x = ha; hp.y = hb;
        H[i] = *(uint32_t*)&hp;
        L[i] = pack_bf2(ra, rb);
    }
    char* dst = (char*)g_P + (size_t)r * ROWB + c * 128 + q * 16;
    *(uint4*)dst        = *(uint4*)H;
    *(uint4*)(dst + 64) = *(uint4*)L;
}

// ---------------- symmetric split-precision HMMA GEMM ----------------
// smem: 2 stages x (A 16KB + B 16KB) = 64KB; epilogue reuses it as fp32 stage.
#define STAGE_BYTES 32768
#define SMEM_BYTES  (66560)   // 1KB align slack + 64KB
#define EPIT 134              // epilogue stage pitch (floats)

__global__ void __launch_bounds__(256)
xxt_hmma_kernel(const float* __restrict__ rho_k, float* __restrict__ C)
{
    const int tileC = blockIdx.x;
    const int tileR = blockIdx.y;
    if (tileC < tileR) return;
    const bool diag = (tileC == tileR);

    extern __shared__ char sm_raw[];
    const uint32_t raw  = smem_u32(sm_raw);
    const uint32_t base = (raw + 1023) & ~1023u;

    const int tid  = threadIdx.x;
    const int lane = tid & 31;
    const int warp = tid >> 5;
    const int wr   = warp >> 2;   // 0..1
    const int wc   = warp & 3;    // 0..3

    const int R0 = tileR * 128;
    const int C0 = tileC * 128;

    float acc[4][4][4];
#pragma unroll
    for (int i = 0; i < 4; i++)
#pragma unroll
        for (int j = 0; j < 4; j++)
#pragma unroll
            for (int k = 0; k < 4; k++) acc[i][j][k] = 0.0f;

    const char* gp = (const char*)g_P;

    // ---- chunk loader: A rows R0.., B rows C0.., 128B per row per chunk ----
#define LOAD_CHUNK(cc, ss)                                                     \
    do {                                                                       \
        const uint32_t bA = base + (ss) * STAGE_BYTES;                         \
        _Pragma("unroll")                                                      \
        for (int i = 0; i < 4; i++) {                                          \
            const int idx  = i * 256 + tid;                                    \
            const int row  = idx >> 3;                                         \
            const int unit = idx & 7;                                          \
            const uint32_t so =                                                \
                (uint32_t)(row * 128 + ((unit ^ (row & 7)) << 4));             \
            cp_async16(bA + so,                                                \
                       gp + (size_t)(R0 + row) * ROWB + (cc) * 128 + unit*16); \
            if (!diag)                                                         \
                cp_async16(bA + 16384 + so,                                    \
                           gp + (size_t)(C0 + row) * ROWB + (cc)*128 + unit*16);\
        }                                                                      \
        CP_COMMIT();                                                           \
    } while (0)

    LOAD_CHUNK(0, 0);

    for (int c = 0; c < CHUNKS; c++) {
        if (c + 1 < CHUNKS) {
            LOAD_CHUNK(c + 1, (c + 1) & 1);
            CP_WAIT(1);
        } else {
            CP_WAIT(0);
        }
        __syncthreads();

        const uint32_t bA = base + (c & 1) * STAGE_BYTES;
        const uint32_t bB = diag ? bA : (bA + 16384);

#pragma unroll
        for (int ks = 0; ks < 2; ks++) {
            uint32_t aH[4][4], aL[4][4], bH[4][2], bL[4][2];

            // A fragments: rows wr*64 + mi*16 + (lane&15), unit = half*4 + ks*2 + (lane>>4)
#pragma unroll
            for (int mi = 0; mi < 4; mi++) {
                const int row = wr * 64 + mi * 16 + (lane & 15);
                const int uH  = ks * 2 + (lane >> 4);
                const int uL  = uH + 4;
                const uint32_t adH = bA + row * 128 + ((uH ^ (row & 7)) << 4);
                const uint32_t adL = bA + row * 128 + ((uL ^ (row & 7)) << 4);
                LDSM4(aH[mi][0], aH[mi][1], aH[mi][2], aH[mi][3], adH);
                LDSM4(aL[mi][0], aL[mi][1], aL[mi][2], aL[mi][3], adL);
            }
            // B fragments: rows wc*32 + bj*16 + (lane&15)
#pragma unroll
            for (int bj = 0; bj < 2; bj++) {
                const int row = wc * 32 + bj * 16 + (lane & 15);
                const int uH  = ks * 2 + (lane >> 4);
                const int uL  = uH + 4;
                const uint32_t adH = bB + row * 128 + ((uH ^ (row & 7)) << 4);
                const uint32_t adL = bB + row * 128 + ((uL ^ (row & 7)) << 4);
                uint32_t t0, t1, t2, t3;
                LDSM4(t0, t1, t2, t3, adH);
                bH[2 * bj][0] = t0; bH[2 * bj + 1][0] = t1;
                bH[2 * bj][1] = t2; bH[2 * bj + 1][1] = t3;
                LDSM4(t0, t1, t2, t3, adL);
                bL[2 * bj][0] = t0; bL[2 * bj + 1][0] = t1;
                bL[2 * bj][1] = t2; bL[2 * bj + 1][1] = t3;
            }

            // HH pass
#pragma unroll
            for (int mi = 0; mi < 4; mi++)
#pragma unroll
                for (int nj = 0; nj < 4; nj++)
                    MMA_BF16(acc[mi][nj], aH[mi], bH[nj]);
            // HL pass
#pragma unroll
            for (int mi = 0; mi < 4; mi++)
#pragma unroll
                for (int nj = 0; nj < 4; nj++)
                    MMA_BF16(acc[mi][nj], aH[mi], bL[nj]);
            // LH pass
#pragma unroll
            for (int mi = 0; mi < 4; mi++)
#pragma unroll
                for (int nj = 0; nj < 4; nj++)
                    MMA_BF16(acc[mi][nj], aL[mi], bH[nj]);
        }
        __syncthreads();
    }

    // ---------------- epilogue ----------------
    const float s = __ldg(rho_k);

    // Upper tile: direct register stores (float2, 32B per thread-quad)
#pragma unroll
    for (int mi = 0; mi < 4; mi++) {
#pragma unroll
        for (int nj = 0; nj < 4; nj++) {
            const int row = R0 + wr * 64 + mi * 16 + (lane >> 2);
            const int col = C0 + wc * 32 + nj * 8 + (lane & 3) * 2;
            float2 v0 = make_float2(acc[mi][nj][0] * s, acc[mi][nj][1] * s);
            float2 v1 = make_float2(acc[mi][nj][2] * s, acc[mi][nj][3] * s);
            *(float2*)&C[(size_t)row * NN + col]       = v0;
            *(float2*)&C[(size_t)(row + 8) * NN + col] = v1;
        }
    }

    // Mirror tile (transposed) via smem staging, two 64-row halves
    if (!diag) {
        float* stage = (float*)(sm_raw + (base - raw));
#pragma unroll
        for (int h = 0; h < 2; h++) {
            __syncthreads();
            if (wr == h) {
#pragma unroll
                for (int mi = 0; mi < 4; mi++) {
#pragma unroll
                    for (int nj = 0; nj < 4; nj++) {
                        const int r   = mi * 16 + (lane >> 2);
                        const int col = wc * 32 + nj * 8 + (lane & 3) * 2;
                        float2 v0 = make_float2(acc[mi][nj][0] * s, acc[mi][nj][1] * s);
                        float2 v1 = make_float2(acc[mi][nj][2] * s, acc[mi][nj][3] * s);
                        *(float2*)&stage[(size_t)r * EPIT + col]       = v0;
                        *(float2*)&stage[(size_t)(r + 8) * EPIT + col] = v1;
                    }
                }
            }
            __syncthreads();
            const int m  = tid >> 1;          // mirror row = tile col
            const int rb = (tid & 1) * 32;    // 32 source rows per thread
#pragma unroll
            for (int j = 0; j < 32; j += 4) {
                float4 v;
                v.x = stage[(size_t)(rb + j + 0) * EPIT + m];
                v.y = stage[(size_t)(rb + j + 1) * EPIT + m];
                v.z = stage[(size_t)(rb + j + 2) * EPIT + m];
                v.w = stage[(size_t)(rb + j + 3) * EPIT + m];
                *(float4*)&C[(size_t)(C0 + m) * NN + R0 + h * 64 + rb + j] = v;
            }
        }
    }
}

// ---------------- heads: mu GEMV + softplus variance onto diagonal ----------------
__global__ void __launch_bounds__(256)
heads_kernel(const float* __restrict__ X,
             const float* __restrict__ muK,
             const float* __restrict__ varK,
             const float* __restrict__ muB,
             const float* __restrict__ varB,
             float* __restrict__ outMu,
             float* __restrict__ cov)
{
    const int gwarp = (blockIdx.x * blockDim.x + threadIdx.x) >> 5;
    const int lane  = threadIdx.x & 31;
    if (gwarp >= NN) return;

    const float* xr = X + (size_t)gwarp * DD;
    float smu = 0.0f, sv = 0.0f;
#pragma unroll
    for (int k = lane * 4; k < DD; k += 32 * 4) {
        const float4 xv = *(const float4*)(xr + k);
        const float4 m  = *(const float4*)(muK + k);
        const float4 v  = *(const float4*)(varK + k);
        smu = fmaf(xv.x, m.x, smu); smu = fmaf(xv.y, m.y, smu);
        smu = fmaf(xv.z, m.z, smu); smu = fmaf(xv.w, m.w, smu);
        sv  = fmaf(xv.x, v.x, sv);  sv  = fmaf(xv.y, v.y, sv);
        sv  = fmaf(xv.z, v.z, sv);  sv  = fmaf(xv.w, v.w, sv);
    }
#pragma unroll
    for (int o = 16; o; o >>= 1) {
        smu += __shfl_xor_sync(0xFFFFFFFFu, smu, o);
        sv  += __shfl_xor_sync(0xFFFFFFFFu, sv, o);
    }
    if (lane == 0) {
        outMu[gwarp] = smu + __ldg(muB);
        const float z = sv + __ldg(varB);
        const float d = log1pf(expf(z)) + 1e-8f;
        cov[(size_t)gwarp * NN + gwarp] = d;
    }
}

extern "C" void kernel_launch(void* const* d_in, const int* in_sizes, int n_in,
                              void* d_out, int out_size)
{
    const float* x     = (const float*)d_in[0];
    const float* mu_k  = (const float*)d_in[1];
    const float* rho_k = (const float*)d_in[2];
    const float* var_k = (const float*)d_in[3];
    const float* mu_b  = (const float*)d_in[4];
    const float* var_b = (const float*)d_in[5];

    float* out_mu = (float*)d_out;
    float* cov    = out_mu + NN;

    cudaFuncSetAttribute(xxt_hmma_kernel,
                         cudaFuncAttributeMaxDynamicSharedMemorySize, SMEM_BYTES);

    convert_kernel<<<(NN * 64) / 256, 256>>>(x);
    xxt_hmma_kernel<<<dim3(NT, NT), 256, SMEM_BYTES>>>(rho_k, cov);
    heads_kernel<<<NN / 8, 256>>>(x, mu_k, var_k, mu_b, var_b, out_mu, cov);
}

// round 4
// speedup vs baseline: 2.5999x; 1.0378x over previous
#include <cuda_runtime.h>
#include <cuda_bf16.h>
#include <math.h>
#include <stdint.h>

#define NN 8192
#define DD 512
#define NT 64            // 8192 / 128 tiles per dim
#define CHUNKS 16        // K chunks of 32
#define ROWB 2048        // bytes per packed row: 16 chunks * (32 H + 32 L) bf16

// Packed split-precision X: per row, per 32-k chunk: [32 bf16 H | 32 bf16 L] = 128B
__device__ __align__(128) __nv_bfloat16 g_P[(size_t)NN * 1024];
// softplus variance per row (applied to cov diagonal by diag GEMM tiles)
__device__ float g_diag[NN];

// ---------------- helpers ----------------
__device__ __forceinline__ uint32_t smem_u32(const void* p) {
    uint32_t a;
    asm("{ .reg .u64 t; cvta.to.shared.u64 t, %1; cvt.u32.u64 %0, t; }"
        : "=r"(a) : "l"(p));
    return a;
}
__device__ __forceinline__ void cp_async16(uint32_t sa, const void* ga) {
    asm volatile("cp.async.cg.shared.global [%0], [%1], 16;" :: "r"(sa), "l"(ga));
}
#define CP_COMMIT() asm volatile("cp.async.commit_group;" ::: "memory")
#define CP_WAIT(n)  asm volatile("cp.async.wait_group %0;" :: "n"(n) : "memory")

#define LDSM4(r0, r1, r2, r3, ad) \
    asm volatile("ldmatrix.sync.aligned.m8n8.x4.shared.b16 {%0,%1,%2,%3}, [%4];" \
                 : "=r"(r0), "=r"(r1), "=r"(r2), "=r"(r3) : "r"(ad))

#define MMA_BF16(d, a, b) \
    asm volatile("mma.sync.aligned.m16n8k16.row.col.f32.bf16.bf16.f32 " \
                 "{%0,%1,%2,%3}, {%4,%5,%6,%7}, {%8,%9}, {%0,%1,%2,%3};" \
                 : "+f"((d)[0]), "+f"((d)[1]), "+f"((d)[2]), "+f"((d)[3]) \
                 : "r"((a)[0]), "r"((a)[1]), "r"((a)[2]), "r"((a)[3]), \
                   "r"((b)[0]), "r"((b)[1]))

__device__ __forceinline__ uint32_t pack_bf2(float a, float b) {
    __nv_bfloat162 p;
    p.x = __float2bfloat16(a);
    p.y = __float2bfloat16(b);
    return *(uint32_t*)&p;
}

// ---------------- fused pre-pass ----------------
// One warp per row: reads X once, produces (a) packed H|L bf16 chunks,
// (b) output_mu[row], (c) g_diag[row] = softplus(x . varK + varB) + 1e-8.
__global__ void __launch_bounds__(256)
prep_kernel(const float* __restrict__ X,
            const float* __restrict__ muK,
            const float* __restrict__ varK,
            const float* __restrict__ muB,
            const float* __restrict__ varB,
            float* __restrict__ outMu)
{
    const int row  = blockIdx.x * 8 + (threadIdx.x >> 5);
    const int lane = threadIdx.x & 31;

    const float* xr = X + (size_t)row * DD;
    char* prow = (char*)g_P + (size_t)row * ROWB;

    float smu = 0.0f, sv = 0.0f;
#pragma unroll
    for (int j = 0; j < 4; j++) {
        const int k = lane * 4 + j * 128;
        const float4 xv = *(const float4*)(xr + k);
        const float4 m  = *(const float4*)(muK + k);
        const float4 v  = *(const float4*)(varK + k);
        smu = fmaf(xv.x, m.x, smu); smu = fmaf(xv.y, m.y, smu);
        smu = fmaf(xv.z, m.z, smu); smu = fmaf(xv.w, m.w, smu);
        sv  = fmaf(xv.x, v.x, sv);  sv  = fmaf(xv.y, v.y, sv);
        sv  = fmaf(xv.z, v.z, sv);  sv  = fmaf(xv.w, v.w, sv);

        __nv_bfloat16 h0 = __float2bfloat16(xv.x);
        __nv_bfloat16 h1 = __float2bfloat16(xv.y);
        __nv_bfloat16 h2 = __float2bfloat16(xv.z);
        __nv_bfloat16 h3 = __float2bfloat16(xv.w);
        uint2 Hw, Lw;
        __nv_bfloat162 hp0; hp0.x = h0; hp0.y = h1;
        __nv_bfloat162 hp1; hp1.x = h2; hp1.y = h3;
        Hw.x = *(uint32_t*)&hp0; Hw.y = *(uint32_t*)&hp1;
        Lw.x = pack_bf2(xv.x - __bfloat162float(h0), xv.y - __bfloat162float(h1));
        Lw.y = pack_bf2(xv.z - __bfloat162float(h2), xv.w - __bfloat162float(h3));

        const int c = k >> 5;          // chunk
        const int p = k & 31;          // pos in chunk
        *(uint2*)(prow + c * 128 + p * 2)      = Hw;   // H half
        *(uint2*)(prow + c * 128 + 64 + p * 2) = Lw;   // L half
    }
#pragma unroll
    for (int o = 16; o; o >>= 1) {
        smu += __shfl_xor_sync(0xFFFFFFFFu, smu, o);
        sv  += __shfl_xor_sync(0xFFFFFFFFu, sv, o);
    }
    if (lane == 0) {
        outMu[row] = smu + __ldg(muB);
        const float z = sv + __ldg(varB);
        g_diag[row] = log1pf(expf(z)) + 1e-8f;
    }
}

// ---------------- symmetric split-precision HMMA GEMM ----------------
// smem: 2 stages x (A 16KB + B 16KB) = 64KB; epilogue reuses it as fp32 stage.
#define STAGE_BYTES 32768
#define SMEM_BYTES  (66560)   // 1KB align slack + 64KB
#define EPIT 134              // epilogue stage pitch (floats)

__global__ void __launch_bounds__(256, 2)
xxt_hmma_kernel(const float* __restrict__ rho_k, float* __restrict__ C)
{
    const int tileC = blockIdx.x;
    const int tileR = blockIdx.y;
    if (tileC < tileR) return;
    const bool diag = (tileC == tileR);

    extern __shared__ char sm_raw[];
    const uint32_t raw  = smem_u32(sm_raw);
    const uint32_t base = (raw + 1023) & ~1023u;

    const int tid  = threadIdx.x;
    const int lane = tid & 31;
    const int warp = tid >> 5;
    const int wr   = warp >> 2;   // 0..1
    const int wc   = warp & 3;    // 0..3

    const int R0 = tileR * 128;
    const int C0 = tileC * 128;

    float acc[4][4][4];
#pragma unroll
    for (int i = 0; i < 4; i++)
#pragma unroll
        for (int j = 0; j < 4; j++)
#pragma unroll
            for (int k = 0; k < 4; k++) acc[i][j][k] = 0.0f;

    const char* gp = (const char*)g_P;

#define LOAD_CHUNK(cc, ss)                                                     \
    do {                                                                       \
        const uint32_t bA = base + (ss) * STAGE_BYTES;                         \
        _Pragma("unroll")                                                      \
        for (int i = 0; i < 4; i++) {                                          \
            const int idx  = i * 256 + tid;                                    \
            const int row  = idx >> 3;                                         \
            const int unit = idx & 7;                                          \
            const uint32_t so =                                                \
                (uint32_t)(row * 128 + ((unit ^ (row & 7)) << 4));             \
            cp_async16(bA + so,                                                \
                       gp + (size_t)(R0 + row) * ROWB + (cc) * 128 + unit*16); \
            if (!diag)                                                         \
                cp_async16(bA + 16384 + so,                                    \
                           gp + (size_t)(C0 + row) * ROWB + (cc)*128 + unit*16);\
        }                                                                      \
        CP_COMMIT();                                                           \
    } while (0)

    LOAD_CHUNK(0, 0);

    for (int c = 0; c < CHUNKS; c++) {
        if (c + 1 < CHUNKS) {
            LOAD_CHUNK(c + 1, (c + 1) & 1);
            CP_WAIT(1);
        } else {
            CP_WAIT(0);
        }
        __syncthreads();

        const uint32_t bA = base + (c & 1) * STAGE_BYTES;
        const uint32_t bB = diag ? bA : (bA + 16384);

#pragma unroll
        for (int ks = 0; ks < 2; ks++) {
            uint32_t aH[4][4], bH[4][2], bL[4][2];

            // A-H fragments
#pragma unroll
            for (int mi = 0; mi < 4; mi++) {
                const int row = wr * 64 + mi * 16 + (lane & 15);
                const int uH  = ks * 2 + (lane >> 4);
                const uint32_t adH = bA + row * 128 + ((uH ^ (row & 7)) << 4);
                LDSM4(aH[mi][0], aH[mi][1], aH[mi][2], aH[mi][3], adH);
            }
            // B-H and B-L fragments
#pragma unroll
            for (int bj = 0; bj < 2; bj++) {
                const int row = wc * 32 + bj * 16 + (lane & 15);
                const int uH  = ks * 2 + (lane >> 4);
                const int uL  = uH + 4;
                const uint32_t adH = bB + row * 128 + ((uH ^ (row & 7)) << 4);
                const uint32_t adL = bB + row * 128 + ((uL ^ (row & 7)) << 4);
                uint32_t t0, t1, t2, t3;
                LDSM4(t0, t1, t2, t3, adH);
                bH[2 * bj][0] = t0; bH[2 * bj + 1][0] = t1;
                bH[2 * bj][1] = t2; bH[2 * bj + 1][1] = t3;
                LDSM4(t0, t1, t2, t3, adL);
                bL[2 * bj][0] = t0; bL[2 * bj + 1][0] = t1;
                bL[2 * bj][1] = t2; bL[2 * bj + 1][1] = t3;
            }

            // HH pass
#pragma unroll
            for (int mi = 0; mi < 4; mi++)
#pragma unroll
                for (int nj = 0; nj < 4; nj++)
                    MMA_BF16(acc[mi][nj], aH[mi], bH[nj]);
            // HL pass
#pragma unroll
            for (int mi = 0; mi < 4; mi++)
#pragma unroll
                for (int nj = 0; nj < 4; nj++)
                    MMA_BF16(acc[mi][nj], aH[mi], bL[nj]);

            // A-L fragments (deferred: lowers peak register pressure)
            uint32_t aL[4][4];
#pragma unroll
            for (int mi = 0; mi < 4; mi++) {
                const int row = wr * 64 + mi * 16 + (lane & 15);
                const int uL  = ks * 2 + (lane >> 4) + 4;
                const uint32_t adL = bA + row * 128 + ((uL ^ (row & 7)) << 4);
                LDSM4(aL[mi][0], aL[mi][1], aL[mi][2], aL[mi][3], adL);
            }
            // LH pass
#pragma unroll
            for (int mi = 0; mi < 4; mi++)
#pragma unroll
                for (int nj = 0; nj < 4; nj++)
                    MMA_BF16(acc[mi][nj], aL[mi], bH[nj]);
        }
        __syncthreads();
    }

    // ---------------- epilogue ----------------
    const float s = __ldg(rho_k);

    // Upper tile: direct register stores
#pragma unroll
    for (int mi = 0; mi < 4; mi++) {
#pragma unroll
        for (int nj = 0; nj < 4; nj++) {
            const int row = R0 + wr * 64 + mi * 16 + (lane >> 2);
            const int col = C0 + wc * 32 + nj * 8 + (lane & 3) * 2;
            float2 v0 = make_float2(acc[mi][nj][0] * s, acc[mi][nj][1] * s);
            float2 v1 = make_float2(acc[mi][nj][2] * s, acc[mi][nj][3] * s);
            *(float2*)&C[(size_t)row * NN + col]       = v0;
            *(float2*)&C[(size_t)(row + 8) * NN + col] = v1;
        }
    }

    if (diag) {
        // patch the covariance diagonal with the softplus variance
        __syncthreads();   // order vs the float2 stores above (CTA scope)
        if (tid < 128) {
            const int r = R0 + tid;
            C[(size_t)r * NN + r] = g_diag[r];
        }
    } else {
        // Mirror tile (transposed) via smem staging, two 64-row halves
        float* stage = (float*)(sm_raw + (base - raw));
#pragma unroll
        for (int h = 0; h < 2; h++) {
            __syncthreads();
            if (wr == h) {
#pragma unroll
                for (int mi = 0; mi < 4; mi++) {
#pragma unroll
                    for (int nj = 0; nj < 4; nj++) {
                        const int r   = mi * 16 + (lane >> 2);
                        const int col = wc * 32 + nj * 8 + (lane & 3) * 2;
                        float2 v0 = make_float2(acc[mi][nj][0] * s, acc[mi][nj][1] * s);
                        float2 v1 = make_float2(acc[mi][nj][2] * s, acc[mi][nj][3] * s);
                        *(float2*)&stage[(size_t)r * EPIT + col]       = v0;
                        *(float2*)&stage[(size_t)(r + 8) * EPIT + col] = v1;
                    }
                }
            }
            __syncthreads();
            const int m  = tid >> 1;          // mirror row = tile col
            const int rb = (tid & 1) * 32;    // 32 source rows per thread
#pragma unroll
            for (int j = 0; j < 32; j += 4) {
                float4 v;
                v.x = stage[(size_t)(rb + j + 0) * EPIT + m];
                v.y = stage[(size_t)(rb + j + 1) * EPIT + m];
                v.z = stage[(size_t)(rb + j + 2) * EPIT + m];
                v.w = stage[(size_t)(rb + j + 3) * EPIT + m];
                *(float4*)&C[(size_t)(C0 + m) * NN + R0 + h * 64 + rb + j] = v;
            }
        }
    }
}

extern "C" void kernel_launch(void* const* d_in, const int* in_sizes, int n_in,
                              void* d_out, int out_size)
{
    const float* x     = (const float*)d_in[0];
    const float* mu_k  = (const float*)d_in[1];
    const float* rho_k = (const float*)d_in[2];
    const float* var_k = (const float*)d_in[3];
    const float* mu_b  = (const float*)d_in[4];
    const float* var_b = (const float*)d_in[5];

    float* out_mu = (float*)d_out;
    float* cov    = out_mu + NN;

    cudaFuncSetAttribute(xxt_hmma_kernel,
                         cudaFuncAttributeMaxDynamicSharedMemorySize, SMEM_BYTES);

    prep_kernel<<<NN / 8, 256>>>(x, mu_k, var_k, mu_b, var_b, out_mu);
    xxt_hmma_kernel<<<dim3(NT, NT), 256, SMEM_BYTES>>>(rho_k, cov);
}

// round 5
// speedup vs baseline: 5.0838x; 1.9554x over previous
#include <cuda_runtime.h>
#include <cuda_fp16.h>
#include <math.h>
#include <stdint.h>

#define NN 8192
#define DD 512
#define NT 64            // 8192 / 128 tiles per dim
#define CHUNKS 8         // K chunks of 64 fp16 (128B)
#define ROWB 1024        // bytes per packed fp16 row (512 * 2)

// fp16 copy of X (contiguous row-major), filled by prep_kernel each call
__device__ __align__(128) __half g_P[(size_t)NN * DD];
// softplus variance per row (applied to cov diagonal by diag GEMM tiles)
__device__ float g_diag[NN];

// ---------------- helpers ----------------
__device__ __forceinline__ uint32_t smem_u32(const void* p) {
    uint32_t a;
    asm("{ .reg .u64 t; cvta.to.shared.u64 t, %1; cvt.u32.u64 %0, t; }"
        : "=r"(a) : "l"(p));
    return a;
}
__device__ __forceinline__ void cp_async16(uint32_t sa, const void* ga) {
    asm volatile("cp.async.cg.shared.global [%0], [%1], 16;" :: "r"(sa), "l"(ga));
}
#define CP_COMMIT() asm volatile("cp.async.commit_group;" ::: "memory")
#define CP_WAIT(n)  asm volatile("cp.async.wait_group %0;" :: "n"(n) : "memory")

#define LDSM4(r0, r1, r2, r3, ad) \
    asm volatile("ldmatrix.sync.aligned.m8n8.x4.shared.b16 {%0,%1,%2,%3}, [%4];" \
                 : "=r"(r0), "=r"(r1), "=r"(r2), "=r"(r3) : "r"(ad))

#define MMA_F16(d, a, b) \
    asm volatile("mma.sync.aligned.m16n8k16.row.col.f32.f16.f16.f32 " \
                 "{%0,%1,%2,%3}, {%4,%5,%6,%7}, {%8,%9}, {%0,%1,%2,%3};" \
                 : "+f"((d)[0]), "+f"((d)[1]), "+f"((d)[2]), "+f"((d)[3]) \
                 : "r"((a)[0]), "r"((a)[1]), "r"((a)[2]), "r"((a)[3]), \
                   "r"((b)[0]), "r"((b)[1]))

// ---------------- fused pre-pass ----------------
// One warp per row: reads X once, produces (a) fp16 row copy,
// (b) output_mu[row], (c) g_diag[row] = softplus(x . varK + varB) + 1e-8.
__global__ void __launch_bounds__(256)
prep_kernel(const float* __restrict__ X,
            const float* __restrict__ muK,
            const float* __restrict__ varK,
            const float* __restrict__ muB,
            const float* __restrict__ varB,
            float* __restrict__ outMu)
{
    const int row  = blockIdx.x * 8 + (threadIdx.x >> 5);
    const int lane = threadIdx.x & 31;

    const float* xr = X + (size_t)row * DD;
    char* prow = (char*)g_P + (size_t)row * ROWB;

    float smu = 0.0f, sv = 0.0f;
#pragma unroll
    for (int j = 0; j < 4; j++) {
        const int k = lane * 4 + j * 128;
        const float4 xv = *(const float4*)(xr + k);
        const float4 m  = *(const float4*)(muK + k);
        const float4 v  = *(const float4*)(varK + k);
        smu = fmaf(xv.x, m.x, smu); smu = fmaf(xv.y, m.y, smu);
        smu = fmaf(xv.z, m.z, smu); smu = fmaf(xv.w, m.w, smu);
        sv  = fmaf(xv.x, v.x, sv);  sv  = fmaf(xv.y, v.y, sv);
        sv  = fmaf(xv.z, v.z, sv);  sv  = fmaf(xv.w, v.w, sv);

        __half2 p0 = __floats2half2_rn(xv.x, xv.y);
        __half2 p1 = __floats2half2_rn(xv.z, xv.w);
        uint2 w;
        w.x = *(uint32_t*)&p0;
        w.y = *(uint32_t*)&p1;
        *(uint2*)(prow + k * 2) = w;
    }
#pragma unroll
    for (int o = 16; o; o >>= 1) {
        smu += __shfl_xor_sync(0xFFFFFFFFu, smu, o);
        sv  += __shfl_xor_sync(0xFFFFFFFFu, sv, o);
    }
    if (lane == 0) {
        outMu[row] = smu + __ldg(muB);
        const float z = sv + __ldg(varB);
        g_diag[row] = log1pf(expf(z)) + 1e-8f;
    }
}

// ---------------- symmetric fp16 HMMA GEMM ----------------
// smem: 2 stages x (A 16KB + B 16KB) = 64KB; epilogue reuses it as fp32 stage.
#define STAGE_BYTES 32768
#define SMEM_BYTES  (66560)   // 1KB align slack + 64KB
#define EPIT 134              // epilogue stage pitch (floats)

__global__ void __launch_bounds__(256, 2)
xxt_hmma_kernel(const float* __restrict__ rho_k, float* __restrict__ C)
{
    const int tileC = blockIdx.x;
    const int tileR = blockIdx.y;
    if (tileC < tileR) return;
    const bool diag = (tileC == tileR);

    extern __shared__ char sm_raw[];
    const uint32_t raw  = smem_u32(sm_raw);
    const uint32_t base = (raw + 1023) & ~1023u;

    const int tid  = threadIdx.x;
    const int lane = tid & 31;
    const int warp = tid >> 5;
    const int wr   = warp >> 2;   // 0..1
    const int wc   = warp & 3;    // 0..3

    const int R0 = tileR * 128;
    const int C0 = tileC * 128;

    float acc[4][4][4];
#pragma unroll
    for (int i = 0; i < 4; i++)
#pragma unroll
        for (int j = 0; j < 4; j++)
#pragma unroll
            for (int k = 0; k < 4; k++) acc[i][j][k] = 0.0f;

    const char* gp = (const char*)g_P;

    // chunk = 64 k-elems = 128B per row. A tile 128x128B, B tile same.
#define LOAD_CHUNK(cc, ss)                                                     \
    do {                                                                       \
        const uint32_t bA = base + (ss) * STAGE_BYTES;                         \
        _Pragma("unroll")                                                      \
        for (int i = 0; i < 4; i++) {                                          \
            const int idx  = i * 256 + tid;                                    \
            const int row  = idx >> 3;                                         \
            const int unit = idx & 7;                                          \
            const uint32_t so =                                                \
                (uint32_t)(row * 128 + ((unit ^ (row & 7)) << 4));             \
            cp_async16(bA + so,                                                \
                       gp + (size_t)(R0 + row) * ROWB + (cc) * 128 + unit*16); \
            if (!diag)                                                         \
                cp_async16(bA + 16384 + so,                                    \
                           gp + (size_t)(C0 + row) * ROWB + (cc)*128 + unit*16);\
        }                                                                      \
        CP_COMMIT();                                                           \
    } while (0)

    LOAD_CHUNK(0, 0);

    for (int c = 0; c < CHUNKS; c++) {
        if (c + 1 < CHUNKS) {
            LOAD_CHUNK(c + 1, (c + 1) & 1);
            CP_WAIT(1);
        } else {
            CP_WAIT(0);
        }
        __syncthreads();

        const uint32_t bA = base + (c & 1) * STAGE_BYTES;
        const uint32_t bB = diag ? bA : (bA + 16384);

#pragma unroll
        for (int ks = 0; ks < 4; ks++) {
            uint32_t aF[4][4], bF[4][2];

            // A fragments: rows wr*64 + mi*16 + (lane&15)
#pragma unroll
            for (int mi = 0; mi < 4; mi++) {
                const int row = wr * 64 + mi * 16 + (lane & 15);
                const int u   = ks * 2 + (lane >> 4);
                const uint32_t ad = bA + row * 128 + ((u ^ (row & 7)) << 4);
                LDSM4(aF[mi][0], aF[mi][1], aF[mi][2], aF[mi][3], ad);
            }
            // B fragments: rows wc*32 + bj*16 + (lane&15)
#pragma unroll
            for (int bj = 0; bj < 2; bj++) {
                const int row = wc * 32 + bj * 16 + (lane & 15);
                const int u   = ks * 2 + (lane >> 4);
                const uint32_t ad = bB + row * 128 + ((u ^ (row & 7)) << 4);
                uint32_t t0, t1, t2, t3;
                LDSM4(t0, t1, t2, t3, ad);
                bF[2 * bj][0] = t0; bF[2 * bj + 1][0] = t1;
                bF[2 * bj][1] = t2; bF[2 * bj + 1][1] = t3;
            }

#pragma unroll
            for (int mi = 0; mi < 4; mi++)
#pragma unroll
                for (int nj = 0; nj < 4; nj++)
                    MMA_F16(acc[mi][nj], aF[mi], bF[nj]);
        }
        __syncthreads();
    }

    // ---------------- epilogue ----------------
    const float s = __ldg(rho_k);

    // Upper tile: direct register stores
#pragma unroll
    for (int mi = 0; mi < 4; mi++) {
#pragma unroll
        for (int nj = 0; nj < 4; nj++) {
            const int row = R0 + wr * 64 + mi * 16 + (lane >> 2);
            const int col = C0 + wc * 32 + nj * 8 + (lane & 3) * 2;
            float2 v0 = make_float2(acc[mi][nj][0] * s, acc[mi][nj][1] * s);
            float2 v1 = make_float2(acc[mi][nj][2] * s, acc[mi][nj][3] * s);
            *(float2*)&C[(size_t)row * NN + col]       = v0;
            *(float2*)&C[(size_t)(row + 8) * NN + col] = v1;
        }
    }

    if (diag) {
        // patch the covariance diagonal with the softplus variance
        __syncthreads();   // order vs the float2 stores above (CTA scope)
        if (tid < 128) {
            const int r = R0 + tid;
            C[(size_t)r * NN + r] = g_diag[r];
        }
    } else {
        // Mirror tile (transposed) via smem staging, two 64-row halves
        float* stage = (float*)(sm_raw + (base - raw));
#pragma unroll
        for (int h = 0; h < 2; h++) {
            __syncthreads();
            if (wr == h) {
#pragma unroll
                for (int mi = 0; mi < 4; mi++) {
#pragma unroll
                    for (int nj = 0; nj < 4; nj++) {
                        const int r   = mi * 16 + (lane >> 2);
                        const int col = wc * 32 + nj * 8 + (lane & 3) * 2;
                        float2 v0 = make_float2(acc[mi][nj][0] * s, acc[mi][nj][1] * s);
                        float2 v1 = make_float2(acc[mi][nj][2] * s, acc[mi][nj][3] * s);
                        *(float2*)&stage[(size_t)r * EPIT + col]       = v0;
                        *(float2*)&stage[(size_t)(r + 8) * EPIT + col] = v1;
                    }
                }
            }
            __syncthreads();
            const int m  = tid >> 1;          // mirror row = tile col
            const int rb = (tid & 1) * 32;    // 32 source rows per thread
#pragma unroll
            for (int j = 0; j < 32; j += 4) {
                float4 v;
                v.x = stage[(size_t)(rb + j + 0) * EPIT + m];
                v.y = stage[(size_t)(rb + j + 1) * EPIT + m];
                v.z = stage[(size_t)(rb + j + 2) * EPIT + m];
                v.w = stage[(size_t)(rb + j + 3) * EPIT + m];
                *(float4*)&C[(size_t)(C0 + m) * NN + R0 + h * 64 + rb + j] = v;
            }
        }
    }
}

extern "C" void kernel_launch(void* const* d_in, const int* in_sizes, int n_in,
                              void* d_out, int out_size)
{
    const float* x     = (const float*)d_in[0];
    const float* mu_k  = (const float*)d_in[1];
    const float* rho_k = (const float*)d_in[2];
    const float* var_k = (const float*)d_in[3];
    const float* mu_b  = (const float*)d_in[4];
    const float* var_b = (const float*)d_in[5];

    float* out_mu = (float*)d_out;
    float* cov    = out_mu + NN;

    cudaFuncSetAttribute(xxt_hmma_kernel,
                         cudaFuncAttributeMaxDynamicSharedMemorySize, SMEM_BYTES);

    prep_kernel<<<NN / 8, 256>>>(x, mu_k, var_k, mu_b, var_b, out_mu);
    xxt_hmma_kernel<<<dim3(NT, NT), 256, SMEM_BYTES>>>(rho_k, cov);
}

// round 6
// speedup vs baseline: 5.2114x; 1.0251x over previous
#include <cuda_runtime.h>
#include <cuda_fp16.h>
#include <math.h>
#include <stdint.h>

#define NN 8192
#define DD 512
#define NT 64            // 8192 / 128 tiles per dim
#define CHUNKS 8         // K chunks of 64 fp16 (128B)
#define ROWB 1024        // bytes per packed fp16 row (512 * 2)

// fp16 copy of X (contiguous row-major), filled by prep_kernel each call
__device__ __align__(128) __half g_P[(size_t)NN * DD];
// softplus variance per row (applied to cov diagonal by diag GEMM tiles)
__device__ float g_diag[NN];

// ---------------- helpers ----------------
__device__ __forceinline__ uint32_t smem_u32(const void* p) {
    uint32_t a;
    asm("{ .reg .u64 t; cvta.to.shared.u64 t, %1; cvt.u32.u64 %0, t; }"
        : "=r"(a) : "l"(p));
    return a;
}
__device__ __forceinline__ void cp_async16(uint32_t sa, const void* ga) {
    asm volatile("cp.async.cg.shared.global [%0], [%1], 16;" :: "r"(sa), "l"(ga));
}
#define CP_COMMIT() asm volatile("cp.async.commit_group;" ::: "memory")
#define CP_WAIT(n)  asm volatile("cp.async.wait_group %0;" :: "n"(n) : "memory")

#define LDSM4(r0, r1, r2, r3, ad) \
    asm volatile("ldmatrix.sync.aligned.m8n8.x4.shared.b16 {%0,%1,%2,%3}, [%4];" \
                 : "=r"(r0), "=r"(r1), "=r"(r2), "=r"(r3) : "r"(ad))

#define MMA_F16(d, a, b) \
    asm volatile("mma.sync.aligned.m16n8k16.row.col.f32.f16.f16.f32 " \
                 "{%0,%1,%2,%3}, {%4,%5,%6,%7}, {%8,%9}, {%0,%1,%2,%3};" \
                 : "+f"((d)[0]), "+f"((d)[1]), "+f"((d)[2]), "+f"((d)[3]) \
                 : "r"((a)[0]), "r"((a)[1]), "r"((a)[2]), "r"((a)[3]), \
                   "r"((b)[0]), "r"((b)[1]))

// ---------------- fused pre-pass ----------------
// One warp per row: reads X once, produces (a) fp16 row copy,
// (b) output_mu[row], (c) g_diag[row] = softplus(x . varK + varB) + 1e-8.
__global__ void __launch_bounds__(256)
prep_kernel(const float* __restrict__ X,
            const float* __restrict__ muK,
            const float* __restrict__ varK,
            const float* __restrict__ muB,
            const float* __restrict__ varB,
            float* __restrict__ outMu)
{
    const int row  = blockIdx.x * 8 + (threadIdx.x >> 5);
    const int lane = threadIdx.x & 31;

    const float* xr = X + (size_t)row * DD;
    char* prow = (char*)g_P + (size_t)row * ROWB;

    float smu = 0.0f, sv = 0.0f;
#pragma unroll
    for (int j = 0; j < 4; j++) {
        const int k = lane * 4 + j * 128;
        const float4 xv = *(const float4*)(xr + k);
        const float4 m  = *(const float4*)(muK + k);
        const float4 v  = *(const float4*)(varK + k);
        smu = fmaf(xv.x, m.x, smu); smu = fmaf(xv.y, m.y, smu);
        smu = fmaf(xv.z, m.z, smu); smu = fmaf(xv.w, m.w, smu);
        sv  = fmaf(xv.x, v.x, sv);  sv  = fmaf(xv.y, v.y, sv);
        sv  = fmaf(xv.z, v.z, sv);  sv  = fmaf(xv.w, v.w, sv);

        __half2 p0 = __floats2half2_rn(xv.x, xv.y);
        __half2 p1 = __floats2half2_rn(xv.z, xv.w);
        uint2 w;
        w.x = *(uint32_t*)&p0;
        w.y = *(uint32_t*)&p1;
        *(uint2*)(prow + k * 2) = w;
    }
#pragma unroll
    for (int o = 16; o; o >>= 1) {
        smu += __shfl_xor_sync(0xFFFFFFFFu, smu, o);
        sv  += __shfl_xor_sync(0xFFFFFFFFu, sv, o);
    }
    if (lane == 0) {
        outMu[row] = smu + __ldg(muB);
        const float z = sv + __ldg(varB);
        g_diag[row] = log1pf(expf(z)) + 1e-8f;
    }
}

// ---------------- symmetric fp16 HMMA GEMM ----------------
// 128x128 CTA tile, 4 warps (2x2) of 64x64 each.
// smem: 3 stages x (A 16KB + B 16KB) = 96KB; epilogue reuses as fp32 stage.
#define STAGE_BYTES 32768
#define NSTAGE 3
#define SMEM_BYTES  (1024 + NSTAGE * STAGE_BYTES)   // 99328
#define EPIT 132              // epilogue stage pitch (floats)

__global__ void __launch_bounds__(128, 2)
xxt_hmma_kernel(const float* __restrict__ rho_k, float* __restrict__ C)
{
    const int tileC = blockIdx.x;
    const int tileR = blockIdx.y;
    if (tileC < tileR) return;
    const bool diag = (tileC == tileR);

    extern __shared__ char sm_raw[];
    const uint32_t raw  = smem_u32(sm_raw);
    const uint32_t base = (raw + 1023) & ~1023u;

    const int tid  = threadIdx.x;
    const int lane = tid & 31;
    const int warp = tid >> 5;
    const int wr   = warp >> 1;   // 0..1
    const int wc   = warp & 1;    // 0..1

    const int R0 = tileR * 128;
    const int C0 = tileC * 128;

    float acc[4][8][4];
#pragma unroll
    for (int i = 0; i < 4; i++)
#pragma unroll
        for (int j = 0; j < 8; j++)
#pragma unroll
            for (int k = 0; k < 4; k++) acc[i][j][k] = 0.0f;

    const char* gp = (const char*)g_P;

    // chunk = 64 k-elems = 128B per row. A tile 128x128B, B tile same.
#define LOAD_CHUNK(cc, ss)                                                     \
    do {                                                                       \
        const uint32_t bA = base + (ss) * STAGE_BYTES;                         \
        _Pragma("unroll")                                                      \
        for (int i = 0; i < 8; i++) {                                          \
            const int idx  = i * 128 + tid;                                    \
            const int row  = idx >> 3;                                         \
            const int unit = idx & 7;                                          \
            const uint32_t so =                                                \
                (uint32_t)(row * 128 + ((unit ^ (row & 7)) << 4));             \
            cp_async16(bA + so,                                                \
                       gp + (size_t)(R0 + row) * ROWB + (cc) * 128 + unit*16); \
            if (!diag)                                                         \
                cp_async16(bA + 16384 + so,                                    \
                           gp + (size_t)(C0 + row) * ROWB + (cc)*128 + unit*16);\
        }                                                                      \
        CP_COMMIT();                                                           \
    } while (0)

    LOAD_CHUNK(0, 0);
    LOAD_CHUNK(1, 1);

    for (int c = 0; c < CHUNKS; c++) {
        if (c + 2 < CHUNKS) { CP_WAIT(1); } else { CP_WAIT(0); }
        __syncthreads();   // stage c visible; stage c-1 free to overwrite

        if (c + 2 < CHUNKS) LOAD_CHUNK(c + 2, (c + 2) % NSTAGE);

        const uint32_t bA = base + (c % NSTAGE) * STAGE_BYTES;
        const uint32_t bB = diag ? bA : (bA + 16384);

#pragma unroll
        for (int ks = 0; ks < 4; ks++) {
            uint32_t aF[4][4], bF[8][2];

            // A fragments: rows wr*64 + mi*16 + (lane&15)
#pragma unroll
            for (int mi = 0; mi < 4; mi++) {
                const int row = wr * 64 + mi * 16 + (lane & 15);
                const int u   = ks * 2 + (lane >> 4);
                const uint32_t ad = bA + row * 128 + ((u ^ (row & 7)) << 4);
                LDSM4(aF[mi][0], aF[mi][1], aF[mi][2], aF[mi][3], ad);
            }
            // B fragments: rows wc*64 + bj*16 + (lane&15)
#pragma unroll
            for (int bj = 0; bj < 4; bj++) {
                const int row = wc * 64 + bj * 16 + (lane & 15);
                const int u   = ks * 2 + (lane >> 4);
                const uint32_t ad = bB + row * 128 + ((u ^ (row & 7)) << 4);
                uint32_t t0, t1, t2, t3;
                LDSM4(t0, t1, t2, t3, ad);
                bF[2 * bj][0] = t0; bF[2 * bj + 1][0] = t1;
                bF[2 * bj][1] = t2; bF[2 * bj + 1][1] = t3;
            }

#pragma unroll
            for (int mi = 0; mi < 4; mi++)
#pragma unroll
                for (int nj = 0; nj < 8; nj++)
                    MMA_F16(acc[mi][nj], aF[mi], bF[nj]);
        }
    }

    // ---------------- epilogue ----------------
    const float s = __ldg(rho_k);

    // Upper tile: direct register stores
#pragma unroll
    for (int mi = 0; mi < 4; mi++) {
#pragma unroll
        for (int nj = 0; nj < 8; nj++) {
            const int row = R0 + wr * 64 + mi * 16 + (lane >> 2);
            const int col = C0 + wc * 64 + nj * 8 + (lane & 3) * 2;
            float2 v0 = make_float2(acc[mi][nj][0] * s, acc[mi][nj][1] * s);
            float2 v1 = make_float2(acc[mi][nj][2] * s, acc[mi][nj][3] * s);
            *(float2*)&C[(size_t)row * NN + col]       = v0;
            *(float2*)&C[(size_t)(row + 8) * NN + col] = v1;
        }
    }

    if (diag) {
        // patch the covariance diagonal with the softplus variance
        __syncthreads();   // order vs the float2 stores above (CTA scope)
        const int r = R0 + tid;
        C[(size_t)r * NN + r] = g_diag[r];
    } else {
        // Mirror tile (transposed) via full-tile smem staging
        float* stage = (float*)(sm_raw + (base - raw));
        __syncthreads();   // all warps done reading pipeline smem
#pragma unroll
        for (int mi = 0; mi < 4; mi++) {
#pragma unroll
            for (int nj = 0; nj < 8; nj++) {
                const int r   = wr * 64 + mi * 16 + (lane >> 2);
                const int col = wc * 64 + nj * 8 + (lane & 3) * 2;
                float2 v0 = make_float2(acc[mi][nj][0] * s, acc[mi][nj][1] * s);
                float2 v1 = make_float2(acc[mi][nj][2] * s, acc[mi][nj][3] * s);
                *(float2*)&stage[(size_t)r * EPIT + col]       = v0;
                *(float2*)&stage[(size_t)(r + 8) * EPIT + col] = v1;
            }
        }
        __syncthreads();
        const int m = tid;  // mirror row = tile col
#pragma unroll 8
        for (int j = 0; j < 128; j += 4) {
            float4 v;
            v.x = stage[(size_t)(j + 0) * EPIT + m];
            v.y = stage[(size_t)(j + 1) * EPIT + m];
            v.z = stage[(size_t)(j + 2) * EPIT + m];
            v.w = stage[(size_t)(j + 3) * EPIT + m];
            *(float4*)&C[(size_t)(C0 + m) * NN + R0 + j] = v;
        }
    }
}

extern "C" void kernel_launch(void* const* d_in, const int* in_sizes, int n_in,
                              void* d_out, int out_size)
{
    const float* x     = (const float*)d_in[0];
    const float* mu_k  = (const float*)d_in[1];
    const float* rho_k = (const float*)d_in[2];
    const float* var_k = (const float*)d_in[3];
    const float* mu_b  = (const float*)d_in[4];
    const float* var_b = (const float*)d_in[5];

    float* out_mu = (float*)d_out;
    float* cov    = out_mu + NN;

    cudaFuncSetAttribute(xxt_hmma_kernel,
                         cudaFuncAttributeMaxDynamicSharedMemorySize, SMEM_BYTES);

    prep_kernel<<<NN / 8, 256>>>(x, mu_k, var_k, mu_b, var_b, out_mu);
    xxt_hmma_kernel<<<dim3(NT, NT), 128, SMEM_BYTES>>>(rho_k, cov);
}

// round 7
// speedup vs baseline: 5.2327x; 1.0041x over previous
#include <cuda_runtime.h>
#include <cuda_fp16.h>
#include <math.h>
#include <stdint.h>

#define NN 8192
#define DD 512
#define NT 64            // 8192 / 128 tiles per dim
#define CHUNKS 8         // K chunks of 64 fp16 (128B)
#define ROWB 1024        // bytes per packed fp16 row (512 * 2)

// fp16 copy of X (contiguous row-major), filled by prep_kernel each call
__device__ __align__(128) __half g_P[(size_t)NN * DD];
// softplus variance per row (applied to cov diagonal by diag GEMM tiles)
__device__ float g_diag[NN];

// ---------------- helpers ----------------
__device__ __forceinline__ uint32_t smem_u32(const void* p) {
    uint32_t a;
    asm("{ .reg .u64 t; cvta.to.shared.u64 t, %1; cvt.u32.u64 %0, t; }"
        : "=r"(a) : "l"(p));
    return a;
}
__device__ __forceinline__ void cp_async16(uint32_t sa, const void* ga) {
    asm volatile("cp.async.cg.shared.global [%0], [%1], 16;" :: "r"(sa), "l"(ga));
}
#define CP_COMMIT() asm volatile("cp.async.commit_group;" ::: "memory")
#define CP_WAIT(n)  asm volatile("cp.async.wait_group %0;" :: "n"(n) : "memory")

#define LDSM4(r0, r1, r2, r3, ad) \
    asm volatile("ldmatrix.sync.aligned.m8n8.x4.shared.b16 {%0,%1,%2,%3}, [%4];" \
                 : "=r"(r0), "=r"(r1), "=r"(r2), "=r"(r3) : "r"(ad))

#define MMA_F16(d, a, b) \
    asm volatile("mma.sync.aligned.m16n8k16.row.col.f32.f16.f16.f32 " \
                 "{%0,%1,%2,%3}, {%4,%5,%6,%7}, {%8,%9}, {%0,%1,%2,%3};" \
                 : "+f"((d)[0]), "+f"((d)[1]), "+f"((d)[2]), "+f"((d)[3]) \
                 : "r"((a)[0]), "r"((a)[1]), "r"((a)[2]), "r"((a)[3]), \
                   "r"((b)[0]), "r"((b)[1]))

// ---------------- fused pre-pass ----------------
__global__ void __launch_bounds__(256)
prep_kernel(const float* __restrict__ X,
            const float* __restrict__ muK,
            const float* __restrict__ varK,
            const float* __restrict__ muB,
            const float* __restrict__ varB,
            float* __restrict__ outMu)
{
    const int row  = blockIdx.x * 8 + (threadIdx.x >> 5);
    const int lane = threadIdx.x & 31;

    const float* xr = X + (size_t)row * DD;
    char* prow = (char*)g_P + (size_t)row * ROWB;

    float smu = 0.0f, sv = 0.0f;
#pragma unroll
    for (int j = 0; j < 4; j++) {
        const int k = lane * 4 + j * 128;
        const float4 xv = *(const float4*)(xr + k);
        const float4 m  = *(const float4*)(muK + k);
        const float4 v  = *(const float4*)(varK + k);
        smu = fmaf(xv.x, m.x, smu); smu = fmaf(xv.y, m.y, smu);
        smu = fmaf(xv.z, m.z, smu); smu = fmaf(xv.w, m.w, smu);
        sv  = fmaf(xv.x, v.x, sv);  sv  = fmaf(xv.y, v.y, sv);
        sv  = fmaf(xv.z, v.z, sv);  sv  = fmaf(xv.w, v.w, sv);

        __half2 p0 = __floats2half2_rn(xv.x, xv.y);
        __half2 p1 = __floats2half2_rn(xv.z, xv.w);
        uint2 w;
        w.x = *(uint32_t*)&p0;
        w.y = *(uint32_t*)&p1;
        *(uint2*)(prow + k * 2) = w;
    }
#pragma unroll
    for (int o = 16; o; o >>= 1) {
        smu += __shfl_xor_sync(0xFFFFFFFFu, smu, o);
        sv  += __shfl_xor_sync(0xFFFFFFFFu, sv, o);
    }
    if (lane == 0) {
        outMu[row] = smu + __ldg(muB);
        const float z = sv + __ldg(varB);
        g_diag[row] = log1pf(expf(z)) + 1e-8f;
    }
}

// ---------------- symmetric fp16 HMMA GEMM ----------------
// 128x128 CTA tile, 4 warps (2x2) of 64x64 each, software-pipelined fragments.
#define STAGE_BYTES 32768
#define NSTAGE 3
#define SMEM_BYTES  (1024 + NSTAGE * STAGE_BYTES)   // 99328
#define EPIT 132              // epilogue stage pitch (floats)

__global__ void __launch_bounds__(128, 2)
xxt_hmma_kernel(const float* __restrict__ rho_k, float* __restrict__ C)
{
    const int tileC = blockIdx.x;
    const int tileR = blockIdx.y;
    if (tileC < tileR) return;
    const bool diag = (tileC == tileR);

    extern __shared__ char sm_raw[];
    const uint32_t raw  = smem_u32(sm_raw);
    const uint32_t base = (raw + 1023) & ~1023u;

    const int tid  = threadIdx.x;
    const int lane = tid & 31;
    const int warp = tid >> 5;
    const int wr   = warp >> 1;   // 0..1
    const int wc   = warp & 1;    // 0..1

    const int R0 = tileR * 128;
    const int C0 = tileC * 128;

    float acc[4][8][4];
#pragma unroll
    for (int i = 0; i < 4; i++)
#pragma unroll
        for (int j = 0; j < 8; j++)
#pragma unroll
            for (int k = 0; k < 4; k++) acc[i][j][k] = 0.0f;

    const char* gp = (const char*)g_P;

#define LOAD_CHUNK(cc, ss)                                                     \
    do {                                                                       \
        const uint32_t sb = base + (ss) * STAGE_BYTES;                         \
        _Pragma("unroll")                                                      \
        for (int i = 0; i < 8; i++) {                                          \
            const int idx  = i * 128 + tid;                                    \
            const int row  = idx >> 3;                                         \
            const int unit = idx & 7;                                          \
            const uint32_t so =                                                \
                (uint32_t)(row * 128 + ((unit ^ (row & 7)) << 4));             \
            cp_async16(sb + so,                                                \
                       gp + (size_t)(R0 + row) * ROWB + (cc) * 128 + unit*16); \
            if (!diag)                                                         \
                cp_async16(sb + 16384 + so,                                    \
                           gp + (size_t)(C0 + row) * ROWB + (cc)*128 + unit*16);\
        }                                                                      \
        CP_COMMIT();                                                           \
    } while (0)

    // single A-fragment LDSM for (mi, ks)
#define LOAD_A(dst, mi_, ks_)                                                  \
    do {                                                                       \
        const int row_ = wr * 64 + (mi_) * 16 + (lane & 15);                   \
        const int u_   = (ks_) * 2 + (lane >> 4);                              \
        const uint32_t ad_ = bA + row_ * 128 + ((u_ ^ (row_ & 7)) << 4);       \
        LDSM4((dst)[0], (dst)[1], (dst)[2], (dst)[3], ad_);                    \
    } while (0)

    // one B-slice LDSM (bj = slice) for ks_, into double buffer dst
#define LOAD_B1(dst, bj_, ks_)                                                 \
    do {                                                                       \
        const int row_ = wc * 64 + (bj_) * 16 + (lane & 15);                   \
        const int u_   = (ks_) * 2 + (lane >> 4);                              \
        const uint32_t ad_ = bB + row_ * 128 + ((u_ ^ (row_ & 7)) << 4);       \
        uint32_t t0_, t1_, t2_, t3_;                                           \
        LDSM4(t0_, t1_, t2_, t3_, ad_);                                        \
        (dst)[2*(bj_)][0] = t0_; (dst)[2*(bj_)+1][0] = t1_;                    \
        (dst)[2*(bj_)][1] = t2_; (dst)[2*(bj_)+1][1] = t3_;                    \
    } while (0)

    LOAD_CHUNK(0, 0);
    LOAD_CHUNK(1, 1);

    uint32_t bF[2][8][2];   // B double buffer across ks
    uint32_t aF[2][4];      // A stream buffer across mi

    for (int c = 0; c < CHUNKS; c++) {
        if (c + 2 < CHUNKS) { CP_WAIT(1); } else { CP_WAIT(0); }
        __syncthreads();   // stage c visible; stage c-1 free to overwrite

        if (c + 2 < CHUNKS) LOAD_CHUNK(c + 2, (c + 2) % NSTAGE);

        const uint32_t bA = base + (c % NSTAGE) * STAGE_BYTES;
        const uint32_t bB = diag ? bA : (bA + 16384);

        // pipeline fill: full B for ks=0, A for (mi=0, ks=0)
#pragma unroll
        for (int bj = 0; bj < 4; bj++) LOAD_B1(bF[0], bj, 0);
        LOAD_A(aF[0], 0, 0);

#pragma unroll
        for (int ks = 0; ks < 4; ks++) {
#pragma unroll
            for (int mi = 0; mi < 4; mi++) {
                // prefetch next A fragment (next mi, or mi=0 of next ks)
                if (mi < 3)      LOAD_A(aF[(mi + 1) & 1], mi + 1, ks);
                else if (ks < 3) LOAD_A(aF[0], 0, ks + 1);
                // prefetch one B slice of next ks (spread over the 4 mi batches)
                if (ks < 3)      LOAD_B1(bF[(ks + 1) & 1], mi, ks + 1);

                // 8 MMAs on current fragments
#pragma unroll
                for (int nj = 0; nj < 8; nj++)
                    MMA_F16(acc[mi][nj], aF[mi & 1], bF[ks & 1][nj]);
            }
        }
    }

    // ---------------- epilogue ----------------
    const float s = __ldg(rho_k);

    // Upper tile: direct register stores
#pragma unroll
    for (int mi = 0; mi < 4; mi++) {
#pragma unroll
        for (int nj = 0; nj < 8; nj++) {
            const int row = R0 + wr * 64 + mi * 16 + (lane >> 2);
            const int col = C0 + wc * 64 + nj * 8 + (lane & 3) * 2;
            float2 v0 = make_float2(acc[mi][nj][0] * s, acc[mi][nj][1] * s);
            float2 v1 = make_float2(acc[mi][nj][2] * s, acc[mi][nj][3] * s);
            *(float2*)&C[(size_t)row * NN + col]       = v0;
            *(float2*)&C[(size_t)(row + 8) * NN + col] = v1;
        }
    }

    if (diag) {
        // patch the covariance diagonal with the softplus variance
        __syncthreads();   // order vs the float2 stores above (CTA scope)
        const int r = R0 + tid;
        C[(size_t)r * NN + r] = g_diag[r];
    } else {
        // Mirror tile (transposed) via full-tile smem staging
        float* stage = (float*)(sm_raw + (base - raw));
        __syncthreads();   // all warps done reading pipeline smem
#pragma unroll
        for (int mi = 0; mi < 4; mi++) {
#pragma unroll
            for (int nj = 0; nj < 8; nj++) {
                const int r   = wr * 64 + mi * 16 + (lane >> 2);
                const int col = wc * 64 + nj * 8 + (lane & 3) * 2;
                float2 v0 = make_float2(acc[mi][nj][0] * s, acc[mi][nj][1] * s);
                float2 v1 = make_float2(acc[mi][nj][2] * s, acc[mi][nj][3] * s);
                *(float2*)&stage[(size_t)r * EPIT + col]       = v0;
                *(float2*)&stage[(size_t)(r + 8) * EPIT + col] = v1;
            }
        }
        __syncthreads();
        const int m = tid;  // mirror row = tile col
#pragma unroll 8
        for (int j = 0; j < 128; j += 4) {
            float4 v;
            v.x = stage[(size_t)(j + 0) * EPIT + m];
            v.y = stage[(size_t)(j + 1) * EPIT + m];
            v.z = stage[(size_t)(j + 2) * EPIT + m];
            v.w = stage[(size_t)(j + 3) * EPIT + m];
            *(float4*)&C[(size_t)(C0 + m) * NN + R0 + j] = v;
        }
    }
}

extern "C" void kernel_launch(void* const* d_in, const int* in_sizes, int n_in,
                              void* d_out, int out_size)
{
    const float* x     = (const float*)d_in[0];
    const float* mu_k  = (const float*)d_in[1];
    const float* rho_k = (const float*)d_in[2];
    const float* var_k = (const float*)d_in[3];
    const float* mu_b  = (const float*)d_in[4];
    const float* var_b = (const float*)d_in[5];

    float* out_mu = (float*)d_out;
    float* cov    = out_mu + NN;

    cudaFuncSetAttribute(xxt_hmma_kernel,
                         cudaFuncAttributeMaxDynamicSharedMemorySize, SMEM_BYTES);

    prep_kernel<<<NN / 8, 256>>>(x, mu_k, var_k, mu_b, var_b, out_mu);
    xxt_hmma_kernel<<<dim3(NT, NT), 128, SMEM_BYTES>>>(rho_k, cov);
}